// round 4
// baseline (speedup 1.0000x reference)
#include <cuda_runtime.h>

#define GRID 296
#define NT   512
#define KC   32

typedef unsigned long long ull;

// ---------------- device scratch ----------------
__device__ float g_k [64*64*512];    // k_tok
__device__ float g_kp[64*64*512];    // K' = k @ wq
__device__ float g_v [64*64*512];    // v_tok
__device__ float g_c0[64*64];        // bq . k (masked)
__device__ float g_s[2][64*512];
__device__ float g_r[2][64*512];
__device__ float g_gig[64*1536];     // grep part of gi (+ b_ih)
__device__ float g_gip[8][64*1536];  // gi_r split-K parts
__device__ float g_ghp[8][64*1536];  // gh split-K parts
__device__ float g_pp[16][64*512];   // patch split-K parts
__device__ int   g_ij[2][64*2];
__device__ unsigned g_barc, g_barg;

__device__ __forceinline__ float4 ld4(const float* p){ return *reinterpret_cast<const float4*>(p); }

__device__ __forceinline__ ull pack2(float x){
    ull d; unsigned u = __float_as_uint(x);
    asm("mov.b64 %0, {%1, %1};" : "=l"(d) : "r"(u));
    return d;
}
__device__ __forceinline__ ull fma2(ull a, ull b, ull c){
    ull d;
    asm("fma.rn.f32x2 %0, %1, %2, %3;" : "=l"(d) : "l"(a), "l"(b), "l"(c));
    return d;
}
__device__ __forceinline__ float lo32(ull a){ return __uint_as_float((unsigned)a); }
__device__ __forceinline__ float hi32(ull a){ return __uint_as_float((unsigned)(a>>32)); }

// ---------------- grid barrier ----------------
__device__ __forceinline__ void gsync(){
    __syncthreads();
    if (threadIdx.x == 0){
        volatile unsigned* vg = &g_barg;
        unsigned gen = *vg;
        __threadfence();
        if (atomicAdd(&g_barc, 1u) == GRID-1u){
            atomicExch(&g_barc, 0u);
            __threadfence();
            atomicAdd(&g_barg, 1u);
        } else {
            while (*vg == gen) __nanosleep(32);
            __threadfence();
        }
    }
    __syncthreads();
}

// ---------------- 64 x <=128 tile GEMM, KC=32 double-buffered, f32x2 ------
// C[m,col] = sum_k A[m,k]*Wv[col,k]. wkm=0: W row-major [col][ldw].
// wkm=1: W k-major [k][ldw], pre-offset to col tile.
// epi: 0 raw, 1 +bias, 2 tanh(+bias)
__device__ void gemm_t(const float* __restrict__ A, int lda,
                       const float* __restrict__ W, int ldw, int wkm,
                       int nchunks, int wcols,
                       float* __restrict__ C, int ldc,
                       const float* __restrict__ bias, int epi,
                       float* __restrict__ sh)
{
    float* sA = sh;           // 2 x 32 x 64
    float* sW = sh + 4096;    // 2 x 32 x 128
    const int tid = threadIdx.x;
    const int ty = tid >> 6;          // 0..7 -> rows ty*8..+7
    const int tx = tid & 63;          // cols tx, tx+64

    ull acc[4][2];
#pragma unroll
    for (int p=0;p<4;p++){ acc[p][0]=0ull; acc[p][1]=0ull; }

    const int am  = tid & 63;          // A loader: row
    const int akq = tid >> 6;          // k offsets akq*4
    const int wn  = tid & 127;         // W rm loader: col
    const int wkq = tid >> 7;          // k offsets wkq*8
    const int kk  = tid >> 4;          // W km loader: k row
    const int c8  = (tid & 15) * 8;    // col offset
    const bool wok = wn < wcols;
    const float4 f0 = make_float4(0.f,0.f,0.f,0.f);

    float4 ra, rw0, rw1;
    // load chunk 0
    ra = ld4(A + (size_t)am*lda + akq*4);
    if (wkm){ rw0 = ld4(W + (size_t)kk*ldw + c8); rw1 = ld4(W + (size_t)kk*ldw + c8 + 4); }
    else {
        rw0 = wok ? ld4(W + (size_t)wn*ldw + wkq*8)     : f0;
        rw1 = wok ? ld4(W + (size_t)wn*ldw + wkq*8 + 4) : f0;
    }
    __syncthreads();   // smem may still be in use by previous task
    {
        sA[(akq*4+0)*64+am]=ra.x; sA[(akq*4+1)*64+am]=ra.y;
        sA[(akq*4+2)*64+am]=ra.z; sA[(akq*4+3)*64+am]=ra.w;
        if (wkm){
            *reinterpret_cast<float4*>(sW + kk*128 + c8)     = rw0;
            *reinterpret_cast<float4*>(sW + kk*128 + c8 + 4) = rw1;
        } else {
            sW[(wkq*8+0)*128+wn]=rw0.x; sW[(wkq*8+1)*128+wn]=rw0.y;
            sW[(wkq*8+2)*128+wn]=rw0.z; sW[(wkq*8+3)*128+wn]=rw0.w;
            sW[(wkq*8+4)*128+wn]=rw1.x; sW[(wkq*8+5)*128+wn]=rw1.y;
            sW[(wkq*8+6)*128+wn]=rw1.z; sW[(wkq*8+7)*128+wn]=rw1.w;
        }
    }
    __syncthreads();

    for (int c=0; c<nchunks; c++){
        const bool more = (c+1) < nchunks;
        const int kc = (c+1)*KC;
        if (more){
            ra = ld4(A + (size_t)am*lda + kc + akq*4);
            if (wkm){ rw0 = ld4(W + (size_t)(kc+kk)*ldw + c8); rw1 = ld4(W + (size_t)(kc+kk)*ldw + c8 + 4); }
            else {
                rw0 = wok ? ld4(W + (size_t)wn*ldw + kc + wkq*8)     : f0;
                rw1 = wok ? ld4(W + (size_t)wn*ldw + kc + wkq*8 + 4) : f0;
            }
        }
        const float* cA = sA + (c&1)*KC*64;
        const float* cW = sW + (c&1)*KC*128;
#pragma unroll
        for (int k=0;k<KC;k++){
            ulonglong2 a01 = *reinterpret_cast<const ulonglong2*>(cA + k*64 + ty*8);
            ulonglong2 a23 = *reinterpret_cast<const ulonglong2*>(cA + k*64 + ty*8 + 4);
            ull w0 = pack2(cW[k*128 + tx]);
            ull w1 = pack2(cW[k*128 + tx + 64]);
            acc[0][0]=fma2(a01.x,w0,acc[0][0]); acc[0][1]=fma2(a01.x,w1,acc[0][1]);
            acc[1][0]=fma2(a01.y,w0,acc[1][0]); acc[1][1]=fma2(a01.y,w1,acc[1][1]);
            acc[2][0]=fma2(a23.x,w0,acc[2][0]); acc[2][1]=fma2(a23.x,w1,acc[2][1]);
            acc[3][0]=fma2(a23.y,w0,acc[3][0]); acc[3][1]=fma2(a23.y,w1,acc[3][1]);
        }
        if (more){
            const int bo = (c+1)&1;
            float* dA = sA + bo*KC*64;
            float* dW = sW + bo*KC*128;
            dA[(akq*4+0)*64+am]=ra.x; dA[(akq*4+1)*64+am]=ra.y;
            dA[(akq*4+2)*64+am]=ra.z; dA[(akq*4+3)*64+am]=ra.w;
            if (wkm){
                *reinterpret_cast<float4*>(dW + kk*128 + c8)     = rw0;
                *reinterpret_cast<float4*>(dW + kk*128 + c8 + 4) = rw1;
            } else {
                dW[(wkq*8+0)*128+wn]=rw0.x; dW[(wkq*8+1)*128+wn]=rw0.y;
                dW[(wkq*8+2)*128+wn]=rw0.z; dW[(wkq*8+3)*128+wn]=rw0.w;
                dW[(wkq*8+4)*128+wn]=rw1.x; dW[(wkq*8+5)*128+wn]=rw1.y;
                dW[(wkq*8+6)*128+wn]=rw1.z; dW[(wkq*8+7)*128+wn]=rw1.w;
            }
        }
        __syncthreads();
    }

#pragma unroll
    for (int p=0;p<4;p++){
        const int r0 = ty*8 + 2*p;
#pragma unroll
        for (int j=0;j<2;j++){
            const int col = tx + 64*j;
            if (col < wcols){
                float lo = lo32(acc[p][j]), hi = hi32(acc[p][j]);
                if (epi == 1){ float b = bias[col]; lo += b; hi += b; }
                else if (epi == 2){ float b = bias[col]; lo = tanhf(lo+b); hi = tanhf(hi+b); }
                C[(size_t)r0*ldc + col]     = lo;
                C[(size_t)(r0+1)*ldc + col] = hi;
            }
        }
    }
}

// ---------------- attention task (one batch per CTA) ----------------
__device__ void attn_task(int b, int cu, float* sm)
{
    float* sq  = sm;         // 512
    float* sal = sm + 512;   // 64
    const int tid = threadIdx.x;
    const int w = tid>>5, lane = tid&31;

    sq[tid] = g_s[cu][b*512 + tid];
    __syncthreads();

#pragma unroll
    for (int i=0;i<4;i++){
        const int n = w*4 + i;
        const float* kp = &g_kp[((size_t)b*64 + n)*512];
        float acc = 0.f;
#pragma unroll
        for (int c=0;c<4;c++){
            float4 kv = ld4(kp + c*128 + lane*4);
            float4 qv = ld4(sq + c*128 + lane*4);
            acc = fmaf(kv.x,qv.x,acc); acc = fmaf(kv.y,qv.y,acc);
            acc = fmaf(kv.z,qv.z,acc); acc = fmaf(kv.w,qv.w,acc);
        }
#pragma unroll
        for (int o=16;o>0;o>>=1) acc += __shfl_down_sync(0xffffffffu, acc, o);
        if (lane==0) sal[n] = acc + g_c0[b*64+n];
    }
    __syncthreads();

    if (w==0){
        float x0 = sal[lane], x1 = sal[lane+32];
        float m = fmaxf(x0,x1);
#pragma unroll
        for (int o=16;o>0;o>>=1) m = fmaxf(m, __shfl_xor_sync(0xffffffffu, m, o));
        float e0 = expf(x0-m), e1 = expf(x1-m);
        float s = e0+e1;
#pragma unroll
        for (int o=16;o>0;o>>=1) s += __shfl_xor_sync(0xffffffffu, s, o);
        float inv = 1.f/s;
        sal[lane] = e0*inv; sal[lane+32] = e1*inv;
    }
    __syncthreads();

    // r = alpha @ v
    {
        const float* vb = g_v + (size_t)b*64*512 + tid;
        float a0=0.f,a1=0.f,a2=0.f,a3=0.f;
#pragma unroll 4
        for (int n=0;n<64;n+=4){
            a0 = fmaf(sal[n+0], vb[(size_t)(n+0)*512], a0);
            a1 = fmaf(sal[n+1], vb[(size_t)(n+1)*512], a1);
            a2 = fmaf(sal[n+2], vb[(size_t)(n+2)*512], a2);
            a3 = fmaf(sal[n+3], vb[(size_t)(n+3)*512], a3);
        }
        g_r[cu][b*512+tid] = (a0+a1)+(a2+a3);
    }
}

// ---------------- combine task ----------------
__device__ void combine_task(int b, int u,
                             const float* __restrict__ grep,
                             const float* __restrict__ b_hh,
                             const float* __restrict__ w_loc,
                             const float* __restrict__ b_loc,
                             float* sm)
{
    const int j = threadIdx.x;
    const int base = b*1536;
    const int cu = u&1;

    float ir  = g_gig[base+j];
    float iz  = g_gig[base+512+j];
    float inn = g_gig[base+1024+j];
#pragma unroll
    for (int p=0;p<8;p++){
        const float* gp = &g_gip[p][base];
        ir += gp[j]; iz += gp[512+j]; inn += gp[1024+j];
    }
    float hr = b_hh[j], hz = b_hh[512+j], hn = b_hh[1024+j];
#pragma unroll
    for (int p=0;p<8;p++){
        const float* gp = &g_ghp[p][base];
        hr += gp[j]; hz += gp[512+j]; hn += gp[1024+j];
    }
    float rg = 1.f/(1.f+expf(-(ir+hr)));
    float zg = 1.f/(1.f+expf(-(iz+hz)));
    float ng = tanhf(inn + rg*hn);
    float so = g_s[cu][b*512+j];
    float sn = (1.f-zg)*ng + zg*so;
    g_s[cu^1][b*512+j] = sn;

    float rr = g_r[cu][b*512+j], gg = grep[b*512+j];
    float p0 = sn*w_loc[j]      + rr*w_loc[512+j]  + gg*w_loc[1024+j];
    float p1 = sn*w_loc[1536+j] + rr*w_loc[2048+j] + gg*w_loc[2560+j];

    const int warp = j>>5, lane = j&31;
#pragma unroll
    for (int o=16;o>0;o>>=1){
        p0 += __shfl_xor_sync(0xffffffffu, p0, o);
        p1 += __shfl_xor_sync(0xffffffffu, p1, o);
    }
    if (lane==0){ sm[warp]=p0; sm[16+warp]=p1; }
    __syncthreads();
    if (j==0){
        float l0=b_loc[0], l1=b_loc[1];
#pragma unroll
        for (int w=0;w<16;w++){ l0+=sm[w]; l1+=sm[16+w]; }
        float cx = tanhf(l0), cy = tanhf(l1);
        int jx = (int)rintf(0.5f*(cx+1.f)*127.f);
        int iy = (int)rintf(0.5f*(cy+1.f)*127.f);
        jx = min(127, max(0, jx));
        iy = min(127, max(0, iy));
        g_ij[cu][b*2]   = iy;
        g_ij[cu][b*2+1] = jx;
    }
}

// ---------------- scatter task ----------------
__device__ void scatter_task(int b, int par, const float* __restrict__ b_write,
                             float* __restrict__ out)
{
    const int c = threadIdx.x;
    if (c >= 400) return;
    const int iy = g_ij[par][b*2], jx = g_ij[par][b*2+1];
    float v = b_write[c];
#pragma unroll
    for (int p=0;p<16;p++) v += g_pp[p][b*512+c];
    int ch = c/25, rem = c - ch*25;
    int ki = rem/5, kj = rem - ki*5;
    int row = iy + ki - 2, col = jx + kj - 2;
    if ((unsigned)row < 128u && (unsigned)col < 128u){
        size_t o = (((size_t)b*16 + ch)*128 + row)*128 + col;
        out[o] += v;
    }
}

// ---------------- persistent kernel ----------------
__global__ void __launch_bounds__(NT,2) painter(
    const float* __restrict__ tok,    const float* __restrict__ grep,
    const int*   __restrict__ mask,
    const float* __restrict__ w_init, const float* __restrict__ b_init,
    const float* __restrict__ wq,     const float* __restrict__ bq,
    const float* __restrict__ wk,     const float* __restrict__ bk,
    const float* __restrict__ wv,     const float* __restrict__ bv,
    const float* __restrict__ w_ih,   const float* __restrict__ b_ih,
    const float* __restrict__ w_hh,   const float* __restrict__ b_hh,
    const float* __restrict__ w_write,const float* __restrict__ b_write,
    const float* __restrict__ w_loc,  const float* __restrict__ b_loc,
    float* __restrict__ out, int out_n)
{
    __shared__ float sh[12288];       // 48KB: GEMM double buffers / attn / combine
    const int bid = blockIdx.x, tid = threadIdx.x;

    // ---- P0: k_tok, v_tok, s0, gi_g, zero canvas ----
    for (int task=bid; task<592; task+=GRID){
        if (task < 512){
            int mat = task>>8, rem = task&255;
            int m0 = (rem>>2)*64, n0 = (rem&3)*128;
            gemm_t(tok + (size_t)m0*512, 512,
                   (mat?wv:wk) + (size_t)n0*512, 512, 0, 16, 128,
                   (mat?g_v:g_k) + (size_t)m0*512 + n0, 512,
                   (mat?bv:bk)+n0, 1, sh);
        } else if (task < 516){
            int n0 = (task-512)*128;
            gemm_t(grep, 512, w_init + (size_t)n0*512, 512, 0, 16, 128,
                   g_s[0]+n0, 512, b_init+n0, 2, sh);
        } else if (task < 528){
            int n0 = (task-516)*128;
            gemm_t(grep, 512, w_ih + (size_t)n0*1024 + 512, 1024, 0, 16, 128,
                   g_gig+n0, 1536, b_ih+n0, 1, sh);
        } else {
            int z = task-528;                 // 0..63
            int per4 = (out_n>>2)/64;         // 65536
            float4* p = reinterpret_cast<float4*>(out) + (size_t)z*per4;
            for (int i=tid;i<per4;i+=NT) p[i] = make_float4(0.f,0.f,0.f,0.f);
        }
    }
    gsync();

    // ---- P1: K' (256 tasks) + c0 (256 tasks) ----
    for (int task=bid; task<512; task+=GRID){
        if (task < 256){
            int m0 = (task>>2)*64, n0 = (task&3)*128;
            gemm_t(g_k + (size_t)m0*512, 512, wq + n0, 512, 1, 16, 128,
                   g_kp + (size_t)m0*512 + n0, 512, 0, 0, sh);
        } else {
            int w = tid>>5, lane = tid&31;
            int row = (task-256)*16 + w;
            const float* kp = &g_k[(size_t)row*512];
            float acc = 0.f;
#pragma unroll
            for (int c=0;c<4;c++){
                float4 kv = ld4(kp + c*128 + lane*4);
                float4 bv4 = ld4(bq + c*128 + lane*4);
                acc = fmaf(kv.x,bv4.x,acc); acc = fmaf(kv.y,bv4.y,acc);
                acc = fmaf(kv.z,bv4.z,acc); acc = fmaf(kv.w,bv4.w,acc);
            }
#pragma unroll
            for (int o=16;o>0;o>>=1) acc += __shfl_down_sync(0xffffffffu, acc, o);
            if (lane==0) g_c0[row] = (mask[row]==0) ? -1e9f : acc;
        }
    }
    gsync();

    // ---- 33 pipelined iterations ----
    for (int u=0; u<=32; u++){
        const int cu = u&1;

        // Phase A: gh(96,u<32) + patch_{u-1}(64,u>0) + attn(64,u<32)
        for (int task=bid; task<224; task+=GRID){
            if (task < 96){
                if (u < 32){
                    int n0 = (task%12)*128, kp = task/12;
                    gemm_t(g_s[cu] + kp*64, 512,
                           w_hh + (size_t)n0*512 + kp*64, 512, 0, 2, 128,
                           g_ghp[kp]+n0, 1536, 0, 0, sh);
                }
            } else if (task < 160){
                if (u > 0){
                    int id = task-96;
                    int nt = id&3, kp = id>>2;
                    int n0 = nt*128;
                    const float* Ab = (kp<8) ? (g_s[cu] + kp*64)
                                             : (g_r[(u-1)&1] + (kp-8)*64);
                    gemm_t(Ab, 512, w_write + (size_t)n0*1024 + kp*64, 1024, 0, 2,
                           (nt==3)?16:128, g_pp[kp]+n0, 512, 0, 0, sh);
                }
            } else {
                if (u < 32) attn_task(task-160, cu, sh);
            }
        }
        gsync();

        // Phase B: gi_r(96,u<32) + scatter_{u-1}(64,u>0)
        for (int task=bid; task<160; task+=GRID){
            if (task < 96){
                if (u < 32){
                    int n0 = (task%12)*128, kp = task/12;
                    gemm_t(g_r[cu] + kp*64, 512,
                           w_ih + (size_t)n0*1024 + kp*64, 1024, 0, 2, 128,
                           g_gip[kp]+n0, 1536, 0, 0, sh);
                }
            } else {
                if (u > 0) scatter_task(task-96, (u-1)&1, b_write, out);
            }
        }

        if (u < 32){
            gsync();
            // Phase C: combine (64)
            for (int task=bid; task<64; task+=GRID)
                combine_task(task, u, grep, b_hh, w_loc, b_loc, sh);
            gsync();
        }
    }
}

// ---------------- launch ----------------
extern "C" void kernel_launch(void* const* d_in, const int* in_sizes, int n_in,
                              void* d_out, int out_size)
{
    const float* token_reps = (const float*)d_in[0];
    const float* global_rep = (const float*)d_in[1];
    const int*   mask       = (const int*)  d_in[2];
    const float* w_init     = (const float*)d_in[3];
    const float* b_init     = (const float*)d_in[4];
    const float* wq         = (const float*)d_in[5];
    const float* bq         = (const float*)d_in[6];
    const float* wk         = (const float*)d_in[7];
    const float* bk         = (const float*)d_in[8];
    const float* wv         = (const float*)d_in[9];
    const float* bv         = (const float*)d_in[10];
    const float* w_ih       = (const float*)d_in[11];
    const float* b_ih       = (const float*)d_in[12];
    const float* w_hh       = (const float*)d_in[13];
    const float* b_hh       = (const float*)d_in[14];
    const float* w_write    = (const float*)d_in[15];
    const float* b_write    = (const float*)d_in[16];
    const float* w_loc      = (const float*)d_in[17];
    const float* b_loc      = (const float*)d_in[18];

    painter<<<GRID, NT>>>(token_reps, global_rep, mask,
                          w_init, b_init, wq, bq, wk, bk, wv, bv,
                          w_ih, b_ih, w_hh, b_hh, w_write, b_write,
                          w_loc, b_loc, (float*)d_out, out_size);
}